// round 7
// baseline (speedup 1.0000x reference)
#include <cuda_runtime.h>
#include <math.h>
#include <stdint.h>

// Problem constants: B=4, L=1024, H=512, NH=8, HD=64, rel rows = 2048

__device__ float g_rel[2048 * 64];
__device__ float g_q[4 * 8 * 1024 * 64];      // [b][n][l][d]
__device__ float g_v[4 * 8 * 1024 * 64];
__device__ float g_wqT[512 * 512];            // W_q transposed: [n][k]
__device__ float g_wvT[512 * 512];            // W_v transposed: [n][k]

// ---------------------------------------------------------------------------
// mma.sync helpers (baseline PTX — valid on compute_103)
// ---------------------------------------------------------------------------
__device__ __forceinline__ uint32_t f2tf32(float x) {
    uint32_t u;
    asm("cvt.rna.tf32.f32 %0, %1;" : "=r"(u) : "f"(x));
    return u;
}
__device__ __forceinline__ void mma_tf32(float* c, const uint32_t* a, const uint32_t* b) {
    asm volatile(
        "mma.sync.aligned.m16n8k8.row.col.f32.tf32.tf32.f32 "
        "{%0,%1,%2,%3}, {%4,%5,%6,%7}, {%8,%9}, {%0,%1,%2,%3};"
        : "+f"(c[0]), "+f"(c[1]), "+f"(c[2]), "+f"(c[3])
        : "r"(a[0]), "r"(a[1]), "r"(a[2]), "r"(a[3]), "r"(b[0]), "r"(b[1]));
}

// ---------------------------------------------------------------------------
// Kernel 0: transpose W (H x H) -> [n][k] for coalesced B-tile loads
// ---------------------------------------------------------------------------
__global__ void __launch_bounds__(256) transpose_w_kernel(const float* __restrict__ wq,
                                                          const float* __restrict__ wv) {
    __shared__ float tile[32][33];
    const float* src = (blockIdx.z == 0) ? wq : wv;
    float* dst = (blockIdx.z == 0) ? g_wqT : g_wvT;
    const int k0 = blockIdx.x * 32, n0 = blockIdx.y * 32;
    const int tx = threadIdx.x, ty = threadIdx.y;   // 32 x 8
    #pragma unroll
    for (int i = 0; i < 4; i++)
        tile[ty + i * 8][tx] = src[(size_t)(k0 + ty + i * 8) * 512 + n0 + tx];
    __syncthreads();
    #pragma unroll
    for (int i = 0; i < 4; i++)
        dst[(size_t)(n0 + ty + i * 8) * 512 + k0 + tx] = tile[tx][ty + i * 8];
}

// ---------------------------------------------------------------------------
// Kernel 1: rel[t][d] = emb(t) @ w_r_w + w_r_b   (unchanged, passing)
// ---------------------------------------------------------------------------
__global__ void __launch_bounds__(256) rel_kernel(const float* __restrict__ w_r_w,
                                                  const float* __restrict__ w_r_b) {
    extern __shared__ float rsm[];
    float* Wsm = rsm;            // 512*64
    float* Emb = Wsm + 32768;    // 8*512

    const int tid = threadIdx.x;
    const int r0 = blockIdx.x * 8;
    const float cc = (float)(-9.210340371976184 / 255.0);

    for (int idx = tid * 4; idx < 32768; idx += 1024)
        *(float4*)&Wsm[idx] = *(const float4*)&w_r_w[idx];

    for (int idx = tid; idx < 8 * 512; idx += 256) {
        int row = idx >> 9;
        int h = idx & 511;
        int t = (h < 256) ? h : (h - 256);
        float f = expf((float)t * cc);
        float ang = (float)(r0 + row - 1024) * f;
        Emb[idx] = (h < 256) ? sinf(ang) : cosf(ang);
    }
    __syncthreads();

    const int d = tid & 63;
    const int rl = tid >> 6;
    const float bias = w_r_b[d];
    #pragma unroll
    for (int rr = 0; rr < 2; rr++) {
        int row = rl + 4 * rr;
        float sum = bias;
        const float* e = &Emb[row * 512];
        #pragma unroll 8
        for (int h = 0; h < 512; h++)
            sum = fmaf(e[h], Wsm[h * 64 + d], sum);
        g_rel[(size_t)(r0 + row) * 64 + d] = sum;
    }
}

// ---------------------------------------------------------------------------
// Kernel 2: projections via mma.sync tf32 3-split (3xTF32).
// D(4096x512) = X(4096x512) @ W(512x512) + b, for q and v.
// Block: 256 thr (8 warps as 2Mx4N), CTA tile 128x128, BK=32.
// Warp tile 64x32: 4 m-tiles (m16) x 4 n-tiles (n8), k8 steps.
// smem: A/B tiles as tf32 hi+lo, u32 stride 36 (conflict-free frags).
// ---------------------------------------------------------------------------
__global__ void __launch_bounds__(256) proj_mma_kernel(
    const float* __restrict__ q_in, const float* __restrict__ v_in,
    const float* __restrict__ bq, const float* __restrict__ bv) {

    extern __shared__ uint32_t usm[];
    uint32_t* Ah = usm;                 // 128*36
    uint32_t* Al = Ah + 128 * 36;
    uint32_t* Bh = Al + 128 * 36;
    uint32_t* Bl = Bh + 128 * 36;

    const int tid = threadIdx.x;
    const int lane = tid & 31, r = lane >> 2, cx = lane & 3;
    const int warpM = (tid >> 5) & 1;    // 0..1
    const int warpN = (tid >> 5) >> 1;   // 0..3
    const int m0 = blockIdx.x * 128, n0 = blockIdx.y * 128;
    const bool isv = (blockIdx.z != 0);

    const float* X  = isv ? v_in : q_in;
    const float* WT = isv ? g_wvT : g_wqT;
    const float* bias = isv ? bv : bq;
    float* out = isv ? g_v : g_q;

    float acc[4][4][4] = {};

    for (int kc = 0; kc < 16; kc++) {
        const int k0 = kc * 32;
        if (kc) __syncthreads();          // prior compute done before overwrite
        // fill A (128x32) and B (128x32) as tf32 hi/lo
        #pragma unroll
        for (int i = 0; i < 4; i++) {
            int idx = tid + i * 256;      // 0..1023
            int row = idx >> 3, kq = (idx & 7) * 4;
            float4 xa = *(const float4*)&X[(size_t)(m0 + row) * 512 + k0 + kq];
            float4 xb = *(const float4*)&WT[(size_t)(n0 + row) * 512 + k0 + kq];
            float as[4] = { xa.x, xa.y, xa.z, xa.w };
            float bs[4] = { xb.x, xb.y, xb.z, xb.w };
            #pragma unroll
            for (int j = 0; j < 4; j++) {
                uint32_t h = f2tf32(as[j]);
                Ah[row * 36 + kq + j] = h;
                Al[row * 36 + kq + j] = f2tf32(as[j] - __uint_as_float(h));
                uint32_t g = f2tf32(bs[j]);
                Bh[row * 36 + kq + j] = g;
                Bl[row * 36 + kq + j] = f2tf32(bs[j] - __uint_as_float(g));
            }
        }
        __syncthreads();

        const uint32_t* pAh = Ah + (warpM * 64) * 36;
        const uint32_t* pAl = Al + (warpM * 64) * 36;
        #pragma unroll
        for (int ks = 0; ks < 4; ks++) {
            const int kb = ks * 8;
            uint32_t ah[4][4], al[4][4];
            #pragma unroll
            for (int mt = 0; mt < 4; mt++) {
                int base = (mt * 16 + r) * 36 + kb + cx;
                ah[mt][0] = pAh[base];
                ah[mt][1] = pAh[base + 8 * 36];
                ah[mt][2] = pAh[base + 4];
                ah[mt][3] = pAh[base + 8 * 36 + 4];
                al[mt][0] = pAl[base];
                al[mt][1] = pAl[base + 8 * 36];
                al[mt][2] = pAl[base + 4];
                al[mt][3] = pAl[base + 8 * 36 + 4];
            }
            uint32_t bh[4][2], bl[4][2];
            #pragma unroll
            for (int nt = 0; nt < 4; nt++) {
                int nb = (warpN * 32 + nt * 8 + r) * 36 + kb + cx;
                bh[nt][0] = Bh[nb];
                bh[nt][1] = Bh[nb + 4];
                bl[nt][0] = Bl[nb];
                bl[nt][1] = Bl[nb + 4];
            }
            #pragma unroll
            for (int mt = 0; mt < 4; mt++)
                #pragma unroll
                for (int nt = 0; nt < 4; nt++) {
                    mma_tf32(acc[mt][nt], ah[mt], bh[nt]);
                    mma_tf32(acc[mt][nt], ah[mt], bl[nt]);
                    mma_tf32(acc[mt][nt], al[mt], bh[nt]);
                }
        }
    }

    // epilogue: C frag c0,c1 at (row=r, col=2cx,2cx+1), c2,c3 at (row=r+8, ...)
    #pragma unroll
    for (int mt = 0; mt < 4; mt++) {
        #pragma unroll
        for (int nt = 0; nt < 4; nt++) {
            int j = n0 + warpN * 32 + nt * 8 + 2 * cx;
            int head = j >> 6, d = j & 63;
            float b0 = bias[j], b1 = bias[j + 1];
            #pragma unroll
            for (int half = 0; half < 2; half++) {
                int m = m0 + warpM * 64 + mt * 16 + r + half * 8;
                int bb = m >> 10, l = m & 1023;
                float2 o;
                o.x = acc[mt][nt][half * 2 + 0] + b0;
                o.y = acc[mt][nt][half * 2 + 1] + b1;
                *(float2*)&out[(size_t)((bb * 8 + head) * 1024 + l) * 64 + d] = o;
            }
        }
    }
}

// ---------------------------------------------------------------------------
// Kernel 3: fused attention, fp32, direct-band (unchanged, passing)
// ---------------------------------------------------------------------------
__global__ void __launch_bounds__(256) attn_kernel(
    const float* __restrict__ key,
    const float* __restrict__ r_r_bias,
    const float* __restrict__ r_w_bias,
    const int*   __restrict__ seq_len_p,
    float* __restrict__ out) {

    extern __shared__ float sm[];
    float* QA  = sm;                 // 64 x 65
    float* QB  = QA + 64 * 65;       // 64 x 65
    float* Ks  = QB + 64 * 65;       // 64 x 65
    float* Pm  = Ks + 64 * 65;       // 64 x 65
    float* RB  = Pm + 64 * 65;       // 128 x 65
    float* RE  = RB + 128 * 65;      // 128 x 65
    float* Vs  = RE + 128 * 65;      // 64 x 64

    const int tid = threadIdx.x;
    const int tx = tid & 15, ty = tid >> 4;
    const int tx4 = tx * 4;
    const int i0 = blockIdx.x * 64;
    const int bn = blockIdx.y;
    const int b = bn >> 3, n = bn & 7;
    const int seq = *seq_len_p;

    const float* qptr = g_q + (size_t)bn * 1024 * 64;
    const float* vptr = g_v + (size_t)bn * 1024 * 64;
    const float* kptr = key + (size_t)b * 1024 * 512 + n * 64;

    for (int idx = tid; idx < 1024; idx += 256) {
        int i = idx >> 4; int d4 = (idx & 15) << 2;
        float4 q4 = *(const float4*)&qptr[(size_t)(i0 + i) * 64 + d4];
        float4 rr = *(const float4*)&r_r_bias[n * 64 + d4];
        float4 rw = *(const float4*)&r_w_bias[n * 64 + d4];
        float* pa = &QA[i * 65 + d4];
        pa[0] = q4.x + rr.x; pa[1] = q4.y + rr.y; pa[2] = q4.z + rr.z; pa[3] = q4.w + rr.w;
        float* pb = &QB[i * 65 + d4];
        pb[0] = q4.x + rw.x; pb[1] = q4.y + rw.y; pb[2] = q4.z + rw.z; pb[3] = q4.w + rw.w;
    }

    float m_r[4], l_r[4], acc[4][4];
    #pragma unroll
    for (int r = 0; r < 4; r++) {
        m_r[r] = -INFINITY; l_r[r] = 0.f;
        acc[r][0] = acc[r][1] = acc[r][2] = acc[r][3] = 0.f;
    }

    const int baseB = tx - ty + 63;
    const int baseE = ty - tx + 63;

    const float* pQA = QA + ty * 65;
    const float* pQB = QB + ty * 65;
    const float* pK  = Ks + tx * 65;
    const float* pRB = RB + baseB * 65;
    const float* pRE = RE + baseE * 65;

    for (int jt = 0; jt < 16; jt++) {
        const int j0 = jt * 64;
        __syncthreads();

        for (int idx = tid; idx < 1024; idx += 256) {
            int j = idx >> 4; int d4 = (idx & 15) << 2;
            float4 k4 = *(const float4*)&kptr[(size_t)(j0 + j) * 512 + d4];
            float* pk = &Ks[j * 65 + d4];
            pk[0] = k4.x; pk[1] = k4.y; pk[2] = k4.z; pk[3] = k4.w;
            float4 v4 = *(const float4*)&vptr[(size_t)(j0 + j) * 64 + d4];
            *(float4*)&Vs[j * 64 + d4] = v4;
        }
        const int rbBase = 1024 + j0 - i0 - 63;
        const int reBase = 1024 + i0 - j0 - 63;
        for (int idx = tid; idx < 2048; idx += 256) {
            int u = idx >> 4; int d4 = (idx & 15) << 2;
            int rb_r = rbBase + u; if (rb_r > 2047) rb_r = 2047;
            int re_r = reBase + u; if (re_r > 2047) re_r = 2047;
            float4 b4 = *(const float4*)&g_rel[(size_t)rb_r * 64 + d4];
            float* prb = &RB[u * 65 + d4];
            prb[0] = b4.x; prb[1] = b4.y; prb[2] = b4.z; prb[3] = b4.w;
            float4 e4 = *(const float4*)&g_rel[(size_t)re_r * 64 + d4];
            float* pre = &RE[u * 65 + d4];
            pre[0] = e4.x; pre[1] = e4.y; pre[2] = e4.z; pre[3] = e4.w;
        }
        __syncthreads();

        float s[4][4] = {};
        #pragma unroll 4
        for (int d = 0; d < 64; d++) {
            float qa[4], qb[4], k[4];
            #pragma unroll
            for (int r = 0; r < 4; r++) {
                qa[r] = pQA[r * (16 * 65) + d];
                qb[r] = pQB[r * (16 * 65) + d];
            }
            #pragma unroll
            for (int c = 0; c < 4; c++) k[c] = pK[c * (16 * 65) + d];
            float rb[7], re[7];
            #pragma unroll
            for (int m = 0; m < 7; m++) {
                rb[m] = pRB[(m - 3) * (16 * 65) + d];
                re[m] = pRE[(m - 3) * (16 * 65) + d];
            }
            #pragma unroll
            for (int r = 0; r < 4; r++)
                #pragma unroll
                for (int c = 0; c < 4; c++) {
                    float t = fmaf(qa[r], k[c], s[r][c]);
                    t = fmaf(qb[r], rb[c - r + 3], t);
                    s[r][c] = fmaf(k[c], re[r - c + 3], t);
                }
        }

        #pragma unroll
        for (int c = 0; c < 4; c++) {
            if (j0 + tx + 16 * c >= seq) {
                s[0][c] = -1e30f; s[1][c] = -1e30f; s[2][c] = -1e30f; s[3][c] = -1e30f;
            }
        }
        #pragma unroll
        for (int r = 0; r < 4; r++) {
            float mr = fmaxf(fmaxf(s[r][0], s[r][1]), fmaxf(s[r][2], s[r][3]));
            mr = fmaxf(mr, __shfl_xor_sync(0xffffffffu, mr, 1));
            mr = fmaxf(mr, __shfl_xor_sync(0xffffffffu, mr, 2));
            mr = fmaxf(mr, __shfl_xor_sync(0xffffffffu, mr, 4));
            mr = fmaxf(mr, __shfl_xor_sync(0xffffffffu, mr, 8));
            float mnew = fmaxf(m_r[r], mr);
            float scale = __expf(m_r[r] - mnew);
            float psum = 0.f;
            float* prow = &Pm[(ty + 16 * r) * 65 + tx];
            #pragma unroll
            for (int c = 0; c < 4; c++) {
                float p = __expf(s[r][c] - mnew);
                prow[16 * c] = p;
                psum += p;
            }
            psum += __shfl_xor_sync(0xffffffffu, psum, 1);
            psum += __shfl_xor_sync(0xffffffffu, psum, 2);
            psum += __shfl_xor_sync(0xffffffffu, psum, 4);
            psum += __shfl_xor_sync(0xffffffffu, psum, 8);
            l_r[r] = l_r[r] * scale + psum;
            m_r[r] = mnew;
            acc[r][0] *= scale; acc[r][1] *= scale; acc[r][2] *= scale; acc[r][3] *= scale;
        }
        __syncthreads();

        #pragma unroll 4
        for (int jj = 0; jj < 64; jj++) {
            float4 v4 = *(const float4*)&Vs[jj * 64 + tx4];
            #pragma unroll
            for (int r = 0; r < 4; r++) {
                float p = Pm[(ty + 16 * r) * 65 + jj];
                acc[r][0] = fmaf(p, v4.x, acc[r][0]);
                acc[r][1] = fmaf(p, v4.y, acc[r][1]);
                acc[r][2] = fmaf(p, v4.z, acc[r][2]);
                acc[r][3] = fmaf(p, v4.w, acc[r][3]);
            }
        }
    }

    #pragma unroll
    for (int r = 0; r < 4; r++) {
        float inv = 1.0f / l_r[r];
        int row = i0 + ty + 16 * r;
        float4 o;
        o.x = acc[r][0] * inv; o.y = acc[r][1] * inv;
        o.z = acc[r][2] * inv; o.w = acc[r][3] * inv;
        *(float4*)&out[(size_t)(b * 1024 + row) * 512 + n * 64 + tx4] = o;
    }
}

// ---------------------------------------------------------------------------
extern "C" void kernel_launch(void* const* d_in, const int* in_sizes, int n_in,
                              void* d_out, int out_size) {
    const float* query    = (const float*)d_in[0];
    const float* key      = (const float*)d_in[1];
    const float* value    = (const float*)d_in[2];
    const float* w_q_w    = (const float*)d_in[3];
    const float* w_q_b    = (const float*)d_in[4];
    const float* w_v_w    = (const float*)d_in[5];
    const float* w_v_b    = (const float*)d_in[6];
    const float* w_r_w    = (const float*)d_in[7];
    const float* w_r_b    = (const float*)d_in[8];
    const float* r_r_bias = (const float*)d_in[9];
    const float* r_w_bias = (const float*)d_in[10];
    const int*   seq_len  = (const int*)d_in[11];
    float* out = (float*)d_out;

    transpose_w_kernel<<<dim3(16, 16, 2), dim3(32, 8)>>>(w_q_w, w_v_w);

    const int rel_smem = (32768 + 4096) * 4;   // 147456
    cudaFuncSetAttribute(rel_kernel, cudaFuncAttributeMaxDynamicSharedMemorySize, rel_smem);
    rel_kernel<<<256, 256, rel_smem>>>(w_r_w, w_r_b);

    const int proj_smem = 4 * 128 * 36 * 4;    // 73728
    cudaFuncSetAttribute(proj_mma_kernel, cudaFuncAttributeMaxDynamicSharedMemorySize, proj_smem);
    proj_mma_kernel<<<dim3(32, 4, 2), 256, proj_smem>>>(query, value, w_q_b, w_v_b);

    const int attn_smem = (4 * 64 * 65 + 2 * 128 * 65 + 64 * 64) * 4;   // 149504
    cudaFuncSetAttribute(attn_kernel, cudaFuncAttributeMaxDynamicSharedMemorySize, attn_smem);
    attn_kernel<<<dim3(16, 32), 256, attn_smem>>>(key, r_r_bias, r_w_bias, seq_len, out);
}

// round 8
// speedup vs baseline: 1.8445x; 1.8445x over previous
#include <cuda_runtime.h>
#include <math.h>
#include <stdint.h>

// Problem constants: B=4, L=1024, H=512, NH=8, HD=64, rel rows = 2048

__device__ float g_rel[2048 * 64];            // rel[t][d]
__device__ float g_relD[8 * 2048];            // delta_n . rel_t  (delta = rw_bias - rr_bias)
__device__ float g_q[4 * 8 * 1024 * 64];      // [b][n][l][d]
__device__ float g_v[4 * 8 * 1024 * 64];

// ---------------------------------------------------------------------------
// Kernel 1: rel[t][d] = emb(t) @ w_r_w + w_r_b   (proven)
// ---------------------------------------------------------------------------
__global__ void __launch_bounds__(256) rel_kernel(const float* __restrict__ w_r_w,
                                                  const float* __restrict__ w_r_b) {
    extern __shared__ float rsm[];
    float* Wsm = rsm;            // 512*64
    float* Emb = Wsm + 32768;    // 8*512

    const int tid = threadIdx.x;
    const int r0 = blockIdx.x * 8;
    const float cc = (float)(-9.210340371976184 / 255.0);

    for (int idx = tid * 4; idx < 32768; idx += 1024)
        *(float4*)&Wsm[idx] = *(const float4*)&w_r_w[idx];

    for (int idx = tid; idx < 8 * 512; idx += 256) {
        int row = idx >> 9;
        int h = idx & 511;
        int t = (h < 256) ? h : (h - 256);
        float f = expf((float)t * cc);
        float ang = (float)(r0 + row - 1024) * f;
        Emb[idx] = (h < 256) ? sinf(ang) : cosf(ang);
    }
    __syncthreads();

    const int d = tid & 63;
    const int rl = tid >> 6;
    const float bias = w_r_b[d];
    #pragma unroll
    for (int rr = 0; rr < 2; rr++) {
        int row = rl + 4 * rr;
        float sum = bias;
        const float* e = &Emb[row * 512];
        #pragma unroll 8
        for (int h = 0; h < 512; h++)
            sum = fmaf(e[h], Wsm[h * 64 + d], sum);
        g_rel[(size_t)(r0 + row) * 64 + d] = sum;
    }
}

// ---------------------------------------------------------------------------
// Kernel 1b: g_relD[n][t] = (r_w_bias[n] - r_r_bias[n]) . g_rel[t]
// 64 blocks x 256 threads; block handles 32 t rows, thread = (t_local, n).
// ---------------------------------------------------------------------------
__global__ void __launch_bounds__(256) reld_kernel(const float* __restrict__ rr_bias,
                                                   const float* __restrict__ rw_bias) {
    __shared__ float relS[32 * 64];
    __shared__ float dS[8 * 64];
    const int tid = threadIdx.x;
    const int t0 = blockIdx.x * 32;

    for (int i = tid; i < 512; i += 256)
        dS[i] = rw_bias[i] - rr_bias[i];
    for (int i = tid * 4; i < 2048; i += 1024)
        *(float4*)&relS[i] = *(const float4*)&g_rel[(size_t)t0 * 64 + i];
    __syncthreads();

    const int tl = tid >> 3, n = tid & 7;
    const float* dn = &dS[n * 64];
    const float* rrow = &relS[tl * 64];
    float s = 0.f;
    #pragma unroll 16
    for (int d = 0; d < 64; d++)
        s = fmaf(dn[d], rrow[d], s);
    g_relD[n * 2048 + t0 + tl] = s;
}

// ---------------------------------------------------------------------------
// Kernel 2: projections q = query@Wq + bq, v = value@Wv + bv  (proven R5 SGEMM)
// ---------------------------------------------------------------------------
__global__ void __launch_bounds__(256) proj_kernel(
    const float* __restrict__ q_in, const float* __restrict__ v_in,
    const float* __restrict__ wq, const float* __restrict__ bq,
    const float* __restrict__ wv, const float* __restrict__ bv) {

    const float* X;  const float* W;  const float* bias;  float* out;
    if (blockIdx.z == 0) { X = q_in; W = wq; bias = bq; out = g_q; }
    else                 { X = v_in; W = wv; bias = bv; out = g_v; }

    __shared__ float As[64][16];
    __shared__ float Bs[16][64];

    const int tid = threadIdx.x;
    const int tx = tid & 15, ty = tid >> 4;
    const int m0 = blockIdx.y * 64;
    const int n0 = blockIdx.x * 64;

    float acc[4][4] = {};

    for (int k0 = 0; k0 < 512; k0 += 16) {
        float4 av = *(const float4*)&X[(size_t)(m0 + (tid >> 2)) * 512 + k0 + (tid & 3) * 4];
        *(float4*)&As[tid >> 2][(tid & 3) * 4] = av;
        float4 bv4 = *(const float4*)&W[(size_t)(k0 + (tid >> 4)) * 512 + n0 + (tid & 15) * 4];
        *(float4*)&Bs[tid >> 4][(tid & 15) * 4] = bv4;
        __syncthreads();

        #pragma unroll
        for (int kk = 0; kk < 16; kk++) {
            float a[4];
            #pragma unroll
            for (int r = 0; r < 4; r++) a[r] = As[ty * 4 + r][kk];
            float4 b4 = *(const float4*)&Bs[kk][tx * 4];
            float b[4] = { b4.x, b4.y, b4.z, b4.w };
            #pragma unroll
            for (int r = 0; r < 4; r++)
                #pragma unroll
                for (int cc = 0; cc < 4; cc++)
                    acc[r][cc] = fmaf(a[r], b[cc], acc[r][cc]);
        }
        __syncthreads();
    }

    float4 bb = *(const float4*)&bias[n0 + tx * 4];
    const int n = blockIdx.x;
    #pragma unroll
    for (int r = 0; r < 4; r++) {
        int m = m0 + ty * 4 + r;
        int b = m >> 10, l = m & 1023;
        float4 o;
        o.x = acc[r][0] + bb.x;  o.y = acc[r][1] + bb.y;
        o.z = acc[r][2] + bb.z;  o.w = acc[r][3] + bb.w;
        *(float4*)&out[(size_t)((b * 8 + n) * 1024 + l) * 64 + tx * 4] = o;
    }
}

// ---------------------------------------------------------------------------
// Kernel 3: fused attention, fp32, direct-band + float2 LDS + QB elimination.
// s[r][c] = QA_i.(K_j) + QA_i.rel[1024+j-i] + K_j.rel[1024+i-j] + relD[n][1024+j-i]
// smem stride 66 (8B-aligned rows for float2), Vs stride 64.
// ---------------------------------------------------------------------------
__global__ void __launch_bounds__(256, 1) attn_kernel(
    const float* __restrict__ key,
    const float* __restrict__ r_r_bias,
    const int*   __restrict__ seq_len_p,
    float* __restrict__ out) {

    extern __shared__ float sm[];
    float* QA  = sm;                 // 64 x 66
    float* Ks  = QA + 64 * 66;       // 64 x 66
    float* Pm  = Ks + 64 * 66;       // 64 x 66
    float* RB  = Pm + 64 * 66;       // 128 x 66 (rows 0..126 used)
    float* RE  = RB + 128 * 66;      // 128 x 66
    float* Vs  = RE + 128 * 66;      // 64 x 64

    const int tid = threadIdx.x;
    const int tx = tid & 15, ty = tid >> 4;
    const int tx4 = tx * 4;
    const int i0 = blockIdx.x * 64;
    const int bn = blockIdx.y;
    const int b = bn >> 3, n = bn & 7;
    const int seq = *seq_len_p;

    const float* qptr = g_q + (size_t)bn * 1024 * 64;
    const float* vptr = g_v + (size_t)bn * 1024 * 64;
    const float* kptr = key + (size_t)b * 1024 * 512 + n * 64;
    const float* relD = g_relD + n * 2048;

    // QA = q + r_r_bias
    for (int idx = tid; idx < 1024; idx += 256) {
        int i = idx >> 4; int d4 = (idx & 15) << 2;
        float4 q4 = *(const float4*)&qptr[(size_t)(i0 + i) * 64 + d4];
        float4 rr = *(const float4*)&r_r_bias[n * 64 + d4];
        float* pa = &QA[i * 66 + d4];
        *(float2*)&pa[0] = make_float2(q4.x + rr.x, q4.y + rr.y);
        *(float2*)&pa[2] = make_float2(q4.z + rr.z, q4.w + rr.w);
    }

    float m_r[4], l_r[4], acc[4][4];
    #pragma unroll
    for (int r = 0; r < 4; r++) {
        m_r[r] = -INFINITY; l_r[r] = 0.f;
        acc[r][0] = acc[r][1] = acc[r][2] = acc[r][3] = 0.f;
    }

    const int baseB = tx - ty + 63;   // in [48,78]; band rows used: [0,126]
    const int baseE = ty - tx + 63;

    const float* pQA = QA + ty * 66;
    const float* pK  = Ks + tx * 66;
    const float* pRB = RB + baseB * 66;
    const float* pRE = RE + baseE * 66;

    for (int jt = 0; jt < 16; jt++) {
        const int j0 = jt * 64;
        __syncthreads();   // prev PV done reading Pm/Vs; first iter: QA ready

        // --- tile loads ---
        for (int idx = tid; idx < 1024; idx += 256) {
            int j = idx >> 4; int d4 = (idx & 15) << 2;
            float4 k4 = *(const float4*)&kptr[(size_t)(j0 + j) * 512 + d4];
            float* pk = &Ks[j * 66 + d4];
            *(float2*)&pk[0] = make_float2(k4.x, k4.y);
            *(float2*)&pk[2] = make_float2(k4.z, k4.w);
            float4 v4 = *(const float4*)&vptr[(size_t)(j0 + j) * 64 + d4];
            *(float4*)&Vs[j * 64 + d4] = v4;
        }
        const int rbBase = 1024 + j0 - i0 - 63;
        const int reBase = 1024 + i0 - j0 - 63;
        for (int idx = tid; idx < 2048; idx += 256) {
            int u = idx >> 4; int d4 = (idx & 15) << 2;
            int rb_r = rbBase + u; rb_r = (rb_r > 2047) ? 2047 : rb_r;
            int re_r = reBase + u; re_r = (re_r > 2047) ? 2047 : re_r;
            float4 b4 = *(const float4*)&g_rel[(size_t)rb_r * 64 + d4];
            float* prb = &RB[u * 66 + d4];
            *(float2*)&prb[0] = make_float2(b4.x, b4.y);
            *(float2*)&prb[2] = make_float2(b4.z, b4.w);
            float4 e4 = *(const float4*)&g_rel[(size_t)re_r * 64 + d4];
            float* pre = &RE[u * 66 + d4];
            *(float2*)&pre[0] = make_float2(e4.x, e4.y);
            *(float2*)&pre[2] = make_float2(e4.z, e4.w);
        }
        __syncthreads();

        // issue the (i-independent) relD band loads early to overlap with compute
        float db[7];
        {
            const float* pD = relD + (1024 + j0 - i0 + tx - ty);
            #pragma unroll
            for (int m = 0; m < 7; m++) db[m] = pD[16 * (m - 3)];
        }

        // --- fused AC + B + E score pass (float2 over d) ---
        float s[4][4] = {};
        #pragma unroll 2
        for (int d = 0; d < 64; d += 2) {
            float2 qa[4], k2[4], rb[7], re[7];
            #pragma unroll
            for (int r = 0; r < 4; r++) qa[r] = *(const float2*)&pQA[r * (16 * 66) + d];
            #pragma unroll
            for (int c = 0; c < 4; c++) k2[c] = *(const float2*)&pK[c * (16 * 66) + d];
            #pragma unroll
            for (int m = 0; m < 7; m++) {
                rb[m] = *(const float2*)&pRB[(m - 3) * (16 * 66) + d];
                re[m] = *(const float2*)&pRE[(m - 3) * (16 * 66) + d];
            }
            #pragma unroll
            for (int r = 0; r < 4; r++)
                #pragma unroll
                for (int c = 0; c < 4; c++) {
                    float t0 = fmaf(qa[r].x, k2[c].x, s[r][c]);
                    float t1 = fmaf(qa[r].y, k2[c].y, t0);
                    float t2 = fmaf(qa[r].x, rb[c - r + 3].x, t1);
                    float t3 = fmaf(qa[r].y, rb[c - r + 3].y, t2);
                    float t4 = fmaf(k2[c].x, re[r - c + 3].x, t3);
                    s[r][c]  = fmaf(k2[c].y, re[r - c + 3].y, t4);
                }
        }
        #pragma unroll
        for (int r = 0; r < 4; r++)
            #pragma unroll
            for (int c = 0; c < 4; c++)
                s[r][c] += db[c - r + 3];

        // --- mask + online softmax ---
        #pragma unroll
        for (int c = 0; c < 4; c++) {
            if (j0 + tx + 16 * c >= seq) {
                s[0][c] = -1e30f; s[1][c] = -1e30f; s[2][c] = -1e30f; s[3][c] = -1e30f;
            }
        }
        #pragma unroll
        for (int r = 0; r < 4; r++) {
            float mr = fmaxf(fmaxf(s[r][0], s[r][1]), fmaxf(s[r][2], s[r][3]));
            mr = fmaxf(mr, __shfl_xor_sync(0xffffffffu, mr, 1));
            mr = fmaxf(mr, __shfl_xor_sync(0xffffffffu, mr, 2));
            mr = fmaxf(mr, __shfl_xor_sync(0xffffffffu, mr, 4));
            mr = fmaxf(mr, __shfl_xor_sync(0xffffffffu, mr, 8));
            float mnew = fmaxf(m_r[r], mr);
            float scale = __expf(m_r[r] - mnew);
            float psum = 0.f;
            float* prow = &Pm[(ty + 16 * r) * 66 + tx];
            #pragma unroll
            for (int c = 0; c < 4; c++) {
                float p = __expf(s[r][c] - mnew);
                prow[16 * c] = p;
                psum += p;
            }
            psum += __shfl_xor_sync(0xffffffffu, psum, 1);
            psum += __shfl_xor_sync(0xffffffffu, psum, 2);
            psum += __shfl_xor_sync(0xffffffffu, psum, 4);
            psum += __shfl_xor_sync(0xffffffffu, psum, 8);
            l_r[r] = l_r[r] * scale + psum;
            m_r[r] = mnew;
            acc[r][0] *= scale; acc[r][1] *= scale; acc[r][2] *= scale; acc[r][3] *= scale;
        }
        __syncthreads();

        // --- PV: acc += P . Vs  (float2 over jj) ---
        #pragma unroll 2
        for (int jj = 0; jj < 64; jj += 2) {
            float4 v0 = *(const float4*)&Vs[jj * 64 + tx4];
            float4 v1 = *(const float4*)&Vs[(jj + 1) * 64 + tx4];
            #pragma unroll
            for (int r = 0; r < 4; r++) {
                float2 p = *(const float2*)&Pm[(ty + 16 * r) * 66 + jj];
                acc[r][0] = fmaf(p.x, v0.x, acc[r][0]);
                acc[r][1] = fmaf(p.x, v0.y, acc[r][1]);
                acc[r][2] = fmaf(p.x, v0.z, acc[r][2]);
                acc[r][3] = fmaf(p.x, v0.w, acc[r][3]);
                acc[r][0] = fmaf(p.y, v1.x, acc[r][0]);
                acc[r][1] = fmaf(p.y, v1.y, acc[r][1]);
                acc[r][2] = fmaf(p.y, v1.z, acc[r][2]);
                acc[r][3] = fmaf(p.y, v1.w, acc[r][3]);
            }
        }
    }

    // epilogue
    #pragma unroll
    for (int r = 0; r < 4; r++) {
        float inv = 1.0f / l_r[r];
        int row = i0 + ty + 16 * r;
        float4 o;
        o.x = acc[r][0] * inv; o.y = acc[r][1] * inv;
        o.z = acc[r][2] * inv; o.w = acc[r][3] * inv;
        *(float4*)&out[(size_t)(b * 1024 + row) * 512 + n * 64 + tx4] = o;
    }
}

// ---------------------------------------------------------------------------
extern "C" void kernel_launch(void* const* d_in, const int* in_sizes, int n_in,
                              void* d_out, int out_size) {
    const float* query    = (const float*)d_in[0];
    const float* key      = (const float*)d_in[1];
    const float* value    = (const float*)d_in[2];
    const float* w_q_w    = (const float*)d_in[3];
    const float* w_q_b    = (const float*)d_in[4];
    const float* w_v_w    = (const float*)d_in[5];
    const float* w_v_b    = (const float*)d_in[6];
    const float* w_r_w    = (const float*)d_in[7];
    const float* w_r_b    = (const float*)d_in[8];
    const float* r_r_bias = (const float*)d_in[9];
    const float* r_w_bias = (const float*)d_in[10];
    const int*   seq_len  = (const int*)d_in[11];
    float* out = (float*)d_out;

    const int rel_smem = (32768 + 4096) * 4;   // 147456
    cudaFuncSetAttribute(rel_kernel, cudaFuncAttributeMaxDynamicSharedMemorySize, rel_smem);
    rel_kernel<<<256, 256, rel_smem>>>(w_r_w, w_r_b);
    reld_kernel<<<64, 256>>>(r_r_bias, r_w_bias);

    proj_kernel<<<dim3(8, 64, 2), 256>>>(query, value, w_q_w, w_q_b, w_v_w, w_v_b);

    const int attn_smem = (3 * 64 * 66 + 2 * 128 * 66 + 64 * 64) * 4;   // 134656
    cudaFuncSetAttribute(attn_kernel, cudaFuncAttributeMaxDynamicSharedMemorySize, attn_smem);
    attn_kernel<<<dim3(16, 32), 256, attn_smem>>>(key, r_r_bias, seq_len, out);
}

// round 9
// speedup vs baseline: 1.9071x; 1.0339x over previous
#include <cuda_runtime.h>
#include <math.h>
#include <stdint.h>

// Problem constants: B=4, L=1024, H=512, NH=8, HD=64, rel rows = 2048

__device__ float g_rel[2048 * 64];            // rel[t][d]
__device__ float g_relD[8 * 2048];            // delta_n . rel_t  (delta = rw_bias - rr_bias)
__device__ float g_q[4 * 8 * 1024 * 64];      // [b][n][l][d]
__device__ float g_v[4 * 8 * 1024 * 64];

// ---------------------------------------------------------------------------
// Kernel 1: rel[t][d] = emb(t) @ w_r_w + w_r_b   (proven)
// ---------------------------------------------------------------------------
__global__ void __launch_bounds__(256) rel_kernel(const float* __restrict__ w_r_w,
                                                  const float* __restrict__ w_r_b) {
    extern __shared__ float rsm[];
    float* Wsm = rsm;            // 512*64
    float* Emb = Wsm + 32768;    // 8*512

    const int tid = threadIdx.x;
    const int r0 = blockIdx.x * 8;
    const float cc = (float)(-9.210340371976184 / 255.0);

    for (int idx = tid * 4; idx < 32768; idx += 1024)
        *(float4*)&Wsm[idx] = *(const float4*)&w_r_w[idx];

    for (int idx = tid; idx < 8 * 512; idx += 256) {
        int row = idx >> 9;
        int h = idx & 511;
        int t = (h < 256) ? h : (h - 256);
        float f = expf((float)t * cc);
        float ang = (float)(r0 + row - 1024) * f;
        Emb[idx] = (h < 256) ? sinf(ang) : cosf(ang);
    }
    __syncthreads();

    const int d = tid & 63;
    const int rl = tid >> 6;
    const float bias = w_r_b[d];
    #pragma unroll
    for (int rr = 0; rr < 2; rr++) {
        int row = rl + 4 * rr;
        float sum = bias;
        const float* e = &Emb[row * 512];
        #pragma unroll 8
        for (int h = 0; h < 512; h++)
            sum = fmaf(e[h], Wsm[h * 64 + d], sum);
        g_rel[(size_t)(r0 + row) * 64 + d] = sum;
    }
}

// ---------------------------------------------------------------------------
// Kernel 1b: g_relD[n][t] = (r_w_bias[n] - r_r_bias[n]) . g_rel[t]
// ---------------------------------------------------------------------------
__global__ void __launch_bounds__(256) reld_kernel(const float* __restrict__ rr_bias,
                                                   const float* __restrict__ rw_bias) {
    __shared__ float relS[32 * 64];
    __shared__ float dS[8 * 64];
    const int tid = threadIdx.x;
    const int t0 = blockIdx.x * 32;

    for (int i = tid; i < 512; i += 256)
        dS[i] = rw_bias[i] - rr_bias[i];
    for (int i = tid * 4; i < 2048; i += 1024)
        *(float4*)&relS[i] = *(const float4*)&g_rel[(size_t)t0 * 64 + i];
    __syncthreads();

    const int tl = tid >> 3, n = tid & 7;
    const float* dn = &dS[n * 64];
    const float* rrow = &relS[tl * 64];
    float s = 0.f;
    #pragma unroll 16
    for (int d = 0; d < 64; d++)
        s = fmaf(dn[d], rrow[d], s);
    g_relD[n * 2048 + t0 + tl] = s;
}

// ---------------------------------------------------------------------------
// Kernel 2: projections (proven R5 SGEMM)
// ---------------------------------------------------------------------------
__global__ void __launch_bounds__(256) proj_kernel(
    const float* __restrict__ q_in, const float* __restrict__ v_in,
    const float* __restrict__ wq, const float* __restrict__ bq,
    const float* __restrict__ wv, const float* __restrict__ bv) {

    const float* X;  const float* W;  const float* bias;  float* out;
    if (blockIdx.z == 0) { X = q_in; W = wq; bias = bq; out = g_q; }
    else                 { X = v_in; W = wv; bias = bv; out = g_v; }

    __shared__ float As[64][16];
    __shared__ float Bs[16][64];

    const int tid = threadIdx.x;
    const int tx = tid & 15, ty = tid >> 4;
    const int m0 = blockIdx.y * 64;
    const int n0 = blockIdx.x * 64;

    float acc[4][4] = {};

    for (int k0 = 0; k0 < 512; k0 += 16) {
        float4 av = *(const float4*)&X[(size_t)(m0 + (tid >> 2)) * 512 + k0 + (tid & 3) * 4];
        *(float4*)&As[tid >> 2][(tid & 3) * 4] = av;
        float4 bv4 = *(const float4*)&W[(size_t)(k0 + (tid >> 4)) * 512 + n0 + (tid & 15) * 4];
        *(float4*)&Bs[tid >> 4][(tid & 15) * 4] = bv4;
        __syncthreads();

        #pragma unroll
        for (int kk = 0; kk < 16; kk++) {
            float a[4];
            #pragma unroll
            for (int r = 0; r < 4; r++) a[r] = As[ty * 4 + r][kk];
            float4 b4 = *(const float4*)&Bs[kk][tx * 4];
            float b[4] = { b4.x, b4.y, b4.z, b4.w };
            #pragma unroll
            for (int r = 0; r < 4; r++)
                #pragma unroll
                for (int cc = 0; cc < 4; cc++)
                    acc[r][cc] = fmaf(a[r], b[cc], acc[r][cc]);
        }
        __syncthreads();
    }

    float4 bb = *(const float4*)&bias[n0 + tx * 4];
    const int n = blockIdx.x;
    #pragma unroll
    for (int r = 0; r < 4; r++) {
        int m = m0 + ty * 4 + r;
        int b = m >> 10, l = m & 1023;
        float4 o;
        o.x = acc[r][0] + bb.x;  o.y = acc[r][1] + bb.y;
        o.z = acc[r][2] + bb.z;  o.w = acc[r][3] + bb.w;
        *(float4*)&out[(size_t)((b * 8 + n) * 1024 + l) * 64 + tx * 4] = o;
    }
}

// ---------------------------------------------------------------------------
// Kernel 3: fused attention, 512 threads, d-split across warp halves.
// Half h=0: d in [0,32) + softmax; h=1: d in [32,64) partials -> Pm scratch.
// PV split over jj halves with consistent per-row scaling; combine at epilogue.
// ---------------------------------------------------------------------------
__global__ void __launch_bounds__(512, 1) attn_kernel(
    const float* __restrict__ key,
    const float* __restrict__ r_r_bias,
    const int*   __restrict__ seq_len_p,
    float* __restrict__ out) {

    extern __shared__ float sm[];
    float* QA  = sm;                 // 64 x 66
    float* Ks  = QA + 64 * 66;       // 64 x 66
    float* Pm  = Ks + 64 * 66;       // 64 x 66  (also score-partial scratch)
    float* RB  = Pm + 64 * 66;       // 128 x 66
    float* RE  = RB + 128 * 66;      // 128 x 66
    float* Vs  = RE + 128 * 66;      // 64 x 64  (also epilogue acc buffer)
    float* scS = Vs + 64 * 64;       // 64       (per-row scale broadcast)

    const int tid = threadIdx.x;
    const int h = tid >> 8;             // 0: warps 0-7, 1: warps 8-15
    const int t = tid & 255;
    const int tx = t & 15, ty = t >> 4;
    const int tx4 = tx * 4;
    const int dOff = h * 32;
    const int i0 = blockIdx.x * 64;
    const int bn = blockIdx.y;
    const int b = bn >> 3, n = bn & 7;
    const int seq = *seq_len_p;

    const float* qptr = g_q + (size_t)bn * 1024 * 64;
    const float* vptr = g_v + (size_t)bn * 1024 * 64;
    const float* kptr = key + (size_t)b * 1024 * 512 + n * 64;
    const float* relD = g_relD + n * 2048;

    // QA = q + r_r_bias
    for (int idx = tid; idx < 1024; idx += 512) {
        int i = idx >> 4; int d4 = (idx & 15) << 2;
        float4 q4 = *(const float4*)&qptr[(size_t)(i0 + i) * 64 + d4];
        float4 rr = *(const float4*)&r_r_bias[n * 64 + d4];
        float* pa = &QA[i * 66 + d4];
        *(float2*)&pa[0] = make_float2(q4.x + rr.x, q4.y + rr.y);
        *(float2*)&pa[2] = make_float2(q4.z + rr.z, q4.w + rr.w);
    }

    float m_r[4], l_r[4], acc[4][4];
    #pragma unroll
    for (int r = 0; r < 4; r++) {
        m_r[r] = -INFINITY; l_r[r] = 0.f;
        acc[r][0] = acc[r][1] = acc[r][2] = acc[r][3] = 0.f;
    }

    const int baseB = tx - ty + 63;
    const int baseE = ty - tx + 63;

    const float* pQA = QA + ty * 66 + dOff;
    const float* pK  = Ks + tx * 66 + dOff;
    const float* pRB = RB + baseB * 66 + dOff;
    const float* pRE = RE + baseE * 66 + dOff;

    for (int jt = 0; jt < 16; jt++) {
        const int j0 = jt * 64;
        __syncthreads();   // SYNC_A: prev PV done; first iter: QA ready

        // --- tile loads (512 threads) ---
        for (int idx = tid; idx < 1024; idx += 512) {
            int j = idx >> 4; int d4 = (idx & 15) << 2;
            float4 k4 = *(const float4*)&kptr[(size_t)(j0 + j) * 512 + d4];
            float* pk = &Ks[j * 66 + d4];
            *(float2*)&pk[0] = make_float2(k4.x, k4.y);
            *(float2*)&pk[2] = make_float2(k4.z, k4.w);
            float4 v4 = *(const float4*)&vptr[(size_t)(j0 + j) * 64 + d4];
            *(float4*)&Vs[j * 64 + d4] = v4;
        }
        const int rbBase = 1024 + j0 - i0 - 63;
        const int reBase = 1024 + i0 - j0 - 63;
        for (int idx = tid; idx < 2048; idx += 512) {
            int u = idx >> 4; int d4 = (idx & 15) << 2;
            int rb_r = rbBase + u; rb_r = (rb_r > 2047) ? 2047 : rb_r;
            int re_r = reBase + u; re_r = (re_r > 2047) ? 2047 : re_r;
            float4 b4 = *(const float4*)&g_rel[(size_t)rb_r * 64 + d4];
            float* prb = &RB[u * 66 + d4];
            *(float2*)&prb[0] = make_float2(b4.x, b4.y);
            *(float2*)&prb[2] = make_float2(b4.z, b4.w);
            float4 e4 = *(const float4*)&g_rel[(size_t)re_r * 64 + d4];
            float* pre = &RE[u * 66 + d4];
            *(float2*)&pre[0] = make_float2(e4.x, e4.y);
            *(float2*)&pre[2] = make_float2(e4.z, e4.w);
        }
        __syncthreads();   // SYNC_B: tiles ready

        // --- fused AC + B + E partial score (this half's 32 d) ---
        float s[4][4] = {};
        #pragma unroll 2
        for (int d = 0; d < 32; d += 2) {
            float2 qa[4], k2[4], rb[7], re[7];
            #pragma unroll
            for (int r = 0; r < 4; r++) qa[r] = *(const float2*)&pQA[r * (16 * 66) + d];
            #pragma unroll
            for (int c = 0; c < 4; c++) k2[c] = *(const float2*)&pK[c * (16 * 66) + d];
            #pragma unroll
            for (int m = 0; m < 7; m++) {
                rb[m] = *(const float2*)&pRB[(m - 3) * (16 * 66) + d];
                re[m] = *(const float2*)&pRE[(m - 3) * (16 * 66) + d];
            }
            #pragma unroll
            for (int r = 0; r < 4; r++)
                #pragma unroll
                for (int c = 0; c < 4; c++) {
                    float t0 = fmaf(qa[r].x, k2[c].x, s[r][c]);
                    float t1 = fmaf(qa[r].y, k2[c].y, t0);
                    float t2 = fmaf(qa[r].x, rb[c - r + 3].x, t1);
                    float t3 = fmaf(qa[r].y, rb[c - r + 3].y, t2);
                    float t4 = fmaf(k2[c].x, re[r - c + 3].x, t3);
                    s[r][c]  = fmaf(k2[c].y, re[r - c + 3].y, t4);
                }
        }

        // half 1 publishes partials into Pm scratch
        if (h == 1) {
            #pragma unroll
            for (int r = 0; r < 4; r++) {
                float* prow = &Pm[(ty + 16 * r) * 66 + tx];
                #pragma unroll
                for (int c = 0; c < 4; c++) prow[16 * c] = s[r][c];
            }
        }
        __syncthreads();   // SYNC_C: partials visible

        if (h == 0) {
            // combine partials + relD, mask, softmax; publish P and scale
            float db[7];
            const float* pD = relD + (1024 + j0 - i0 + tx - ty);
            #pragma unroll
            for (int m = 0; m < 7; m++) db[m] = pD[16 * (m - 3)];

            #pragma unroll
            for (int r = 0; r < 4; r++) {
                float* prow = &Pm[(ty + 16 * r) * 66 + tx];
                #pragma unroll
                for (int c = 0; c < 4; c++)
                    s[r][c] += prow[16 * c] + db[c - r + 3];
            }
            #pragma unroll
            for (int c = 0; c < 4; c++) {
                if (j0 + tx + 16 * c >= seq) {
                    s[0][c] = -1e30f; s[1][c] = -1e30f; s[2][c] = -1e30f; s[3][c] = -1e30f;
                }
            }
            #pragma unroll
            for (int r = 0; r < 4; r++) {
                float mr = fmaxf(fmaxf(s[r][0], s[r][1]), fmaxf(s[r][2], s[r][3]));
                mr = fmaxf(mr, __shfl_xor_sync(0xffffffffu, mr, 1));
                mr = fmaxf(mr, __shfl_xor_sync(0xffffffffu, mr, 2));
                mr = fmaxf(mr, __shfl_xor_sync(0xffffffffu, mr, 4));
                mr = fmaxf(mr, __shfl_xor_sync(0xffffffffu, mr, 8));
                float mnew = fmaxf(m_r[r], mr);
                float scale = __expf(m_r[r] - mnew);
                float psum = 0.f;
                float* prow = &Pm[(ty + 16 * r) * 66 + tx];
                #pragma unroll
                for (int c = 0; c < 4; c++) {
                    float p = __expf(s[r][c] - mnew);
                    prow[16 * c] = p;
                    psum += p;
                }
                psum += __shfl_xor_sync(0xffffffffu, psum, 1);
                psum += __shfl_xor_sync(0xffffffffu, psum, 2);
                psum += __shfl_xor_sync(0xffffffffu, psum, 4);
                psum += __shfl_xor_sync(0xffffffffu, psum, 8);
                l_r[r] = l_r[r] * scale + psum;
                m_r[r] = mnew;
                acc[r][0] *= scale; acc[r][1] *= scale; acc[r][2] *= scale; acc[r][3] *= scale;
                if (tx == 0) scS[ty + 16 * r] = scale;
            }
        }
        __syncthreads();   // SYNC_D: P + scales visible

        if (h == 1) {
            #pragma unroll
            for (int r = 0; r < 4; r++) {
                float sc = scS[ty + 16 * r];
                acc[r][0] *= sc; acc[r][1] *= sc; acc[r][2] *= sc; acc[r][3] *= sc;
            }
        }

        // --- PV: this half's 32 jj ---
        const int jb = h * 32;
        #pragma unroll 2
        for (int jj = jb; jj < jb + 32; jj += 2) {
            float4 v0 = *(const float4*)&Vs[jj * 64 + tx4];
            float4 v1 = *(const float4*)&Vs[(jj + 1) * 64 + tx4];
            #pragma unroll
            for (int r = 0; r < 4; r++) {
                float2 p = *(const float2*)&Pm[(ty + 16 * r) * 66 + jj];
                acc[r][0] = fmaf(p.x, v0.x, acc[r][0]);
                acc[r][1] = fmaf(p.x, v0.y, acc[r][1]);
                acc[r][2] = fmaf(p.x, v0.z, acc[r][2]);
                acc[r][3] = fmaf(p.x, v0.w, acc[r][3]);
                acc[r][0] = fmaf(p.y, v1.x, acc[r][0]);
                acc[r][1] = fmaf(p.y, v1.y, acc[r][1]);
                acc[r][2] = fmaf(p.y, v1.z, acc[r][2]);
                acc[r][3] = fmaf(p.y, v1.w, acc[r][3]);
            }
        }
    }

    // epilogue: combine halves through Vs buffer, then scale by 1/l
    __syncthreads();
    if (h == 1) {
        #pragma unroll
        for (int r = 0; r < 4; r++)
            *(float4*)&Vs[(ty + 16 * r) * 64 + tx4] =
                make_float4(acc[r][0], acc[r][1], acc[r][2], acc[r][3]);
    }
    __syncthreads();
    if (h == 0) {
        #pragma unroll
        for (int r = 0; r < 4; r++) {
            float inv = 1.0f / l_r[r];
            float4 a2 = *(const float4*)&Vs[(ty + 16 * r) * 64 + tx4];
            int row = i0 + ty + 16 * r;
            float4 o;
            o.x = (acc[r][0] + a2.x) * inv; o.y = (acc[r][1] + a2.y) * inv;
            o.z = (acc[r][2] + a2.z) * inv; o.w = (acc[r][3] + a2.w) * inv;
            *(float4*)&out[(size_t)(b * 1024 + row) * 512 + n * 64 + tx4] = o;
        }
    }
}

// ---------------------------------------------------------------------------
extern "C" void kernel_launch(void* const* d_in, const int* in_sizes, int n_in,
                              void* d_out, int out_size) {
    const float* query    = (const float*)d_in[0];
    const float* key      = (const float*)d_in[1];
    const float* value    = (const float*)d_in[2];
    const float* w_q_w    = (const float*)d_in[3];
    const float* w_q_b    = (const float*)d_in[4];
    const float* w_v_w    = (const float*)d_in[5];
    const float* w_v_b    = (const float*)d_in[6];
    const float* w_r_w    = (const float*)d_in[7];
    const float* w_r_b    = (const float*)d_in[8];
    const float* r_r_bias = (const float*)d_in[9];
    const float* r_w_bias = (const float*)d_in[10];
    const int*   seq_len  = (const int*)d_in[11];
    float* out = (float*)d_out;

    const int rel_smem = (32768 + 4096) * 4;   // 147456
    cudaFuncSetAttribute(rel_kernel, cudaFuncAttributeMaxDynamicSharedMemorySize, rel_smem);
    rel_kernel<<<256, 256, rel_smem>>>(w_r_w, w_r_b);
    reld_kernel<<<64, 256>>>(r_r_bias, r_w_bias);

    proj_kernel<<<dim3(8, 64, 2), 256>>>(query, value, w_q_w, w_q_b, w_v_w, w_v_b);

    const int attn_smem = (3 * 64 * 66 + 2 * 128 * 66 + 64 * 64 + 64) * 4;   // 134912
    cudaFuncSetAttribute(attn_kernel, cudaFuncAttributeMaxDynamicSharedMemorySize, attn_smem);
    attn_kernel<<<dim3(16, 32), 512, attn_smem>>>(key, r_r_bias, seq_len, out);
}